// round 15
// baseline (speedup 1.0000x reference)
#include <cuda_runtime.h>
#include <stdint.h>

#define T_STEPS 2000
#define BATCH   1024
#define NS      16
#define NA      4
#define STRIDE_T (BATCH * NS)

#define C_CHUNKS 10
#define K_CHUNK  200     // payload timesteps per chunk (C*K = T)
#define HALO     48      // 6 groups of 8: 4 PFC-only + 2 full warm-up

// per-(batch,chunk,action) payload PMC spike counts; every slot written each run
__device__ int g_part[BATCH * C_CHUNKS * NA];
__device__ int g_done = 0;   // block completion counter; reset by the finalizer

__global__ __launch_bounds__(128, 5)
void bg_kernel(const float* __restrict__ pfc,
               const float* __restrict__ w_pfc_d1,
               const float* __restrict__ w_pfc_d2,
               float* __restrict__ out, int out_size)
{
    __shared__ float2 lutA[256][NA];
    __shared__ float2 lutB[256][NA];
    __shared__ int s_last;

    const int tid = threadIdx.x;
    for (int e = tid; e < 512; e += blockDim.x) {
        const int hi = e >> 8;
        const int m  = e & 255;
        const int ibase = hi ? 8 : 0;
        #pragma unroll
        for (int jj = 0; jj < NA; jj++) {
            float a1 = 0.0f, a2 = 0.0f;
            #pragma unroll
            for (int i = 0; i < 8; i++)
                if ((m >> i) & 1) {
                    a1 += w_pfc_d1[(ibase + i) * NA + jj];
                    a2 += w_pfc_d2[(ibase + i) * NA + jj];
                }
            if (hi) lutB[m][jj] = make_float2(a1, a2);
            else    lutA[m][jj] = make_float2(a1, a2);
        }
    }
    __syncthreads();

    const int lane  = tid & 31;
    const int w     = blockIdx.x * 4 + (tid >> 5);  // global warp 0..2559
    const int quad  = w / C_CHUNKS;                 // batch quad 0..255
    const int chunk = w - quad * C_CHUNKS;          // 0..9
    const int grp   = lane >> 3;                    // batch-within-warp 0..3
    const int pos   = lane & 7;                     // neuron index (also pos+8)
    const int b     = quad * 4 + grp;
    const int j     = pos & 3;
    const unsigned sel = 0x4440u | (unsigned)grp;   // extract byte grp, zero-extend

    const unsigned long long NEG1 = 0xBF800000BF800000ULL;  // (-1.0f, -1.0f)

    // pathway weights, exact reference fp32 op order
    const float w1j = (j == 0) ? 0.2f : (j == 1) ? 0.12f : (j == 2) ? 0.07f : 0.03f;
    const float w2j = (j == 0) ? 0.03f : (j == 1) ? 0.07f : (j == 2) ? 0.12f : 0.2f;
    const float W_D1_GPI   = (-1.0f * w1j) * 5.0f;
    const float W_D2_GPE   = (-1.0f * w1j) * 5.0f;
    const float W_GPE_STN  = (-0.8f * w1j) * 5.0f;
    const float W_STN_GPI  = (1.2f  * w1j) * 5.0f;
    const float W_GPI_THAL = (-1.0f * w2j) * 5.0f;
    const float W_THAL_PMC = (1.0f  * w1j) * 5.0f;

    // GPE..PMC exactly stateless => s_pmc = f(s_d1, s_d2); 4-entry truth table
    // built with one exact LIF step per layer from v=0 (v' = x exactly).
    int tt = 0;
    #pragma unroll
    for (int cb = 0; cb < 4; cb++) {
        float sd1 = (cb & 2) ? 1.0f : 0.0f;
        float sd2 = (cb & 1) ? 1.0f : 0.0f;
        float xg = sd2 * W_D2_GPE + 1.5f;
        float sg = (xg >= 1.0f) ? 1.0f : 0.0f;
        float xs = sg * W_GPE_STN + 1.8f;
        float ss = (xs >= 1.0f) ? 1.0f : 0.0f;
        float xi = (sd1 * W_D1_GPI + ss * W_STN_GPI) + 1.5f;
        float si = (xi >= 1.0f) ? 1.0f : 0.0f;
        float xt = si * W_GPI_THAL + 1.2f;
        float st = (xt >= 1.0f) ? 1.0f : 0.0f;
        float xp = st * W_THAL_PMC + 0.5f;
        if (xp >= 1.0f) tt |= 1 << cb;
    }
    const unsigned u00 = tt & 1, u01 = (tt >> 1) & 1,
                   u10 = (tt >> 2) & 1, u11 = (tt >> 3) & 1;

    // chunk geometry: ngroups groups of 8 steps
    const int t0    = chunk * K_CHUNK - (chunk ? HALO : 0);
    const int npair = chunk ? 15 : 12;   // (ngroups-1)/2, ngroups = 31 or 25
    const int P     = chunk ? 4 : 0;     // first P groups: PFC-only warm-up
    const int ZG    = chunk ? 6 : 0;     // zero acc before B of (group ZG, k==1)

    float v0 = 0.0f, v1 = 0.0f, vd1 = 0.0f, vd2 = 0.0f;
    int acc = 0;
    unsigned m_lo = 0, m_hi = 0;   // skew registers: ballots of the previous step

    // stage B: previous step's masks -> LUT (LDS.64 pairs) -> packed f32x2
    // striatal LIF -> truth-table count. Per-half rn rounding identical to the
    // scalar sequence (fma product with -1 is exact).
    #define STAGE_B()                                                      \
    {                                                                      \
        unsigned mlo = __byte_perm(m_lo, 0u, sel);                         \
        unsigned mhi = __byte_perm(m_hi, 0u, sel);                         \
        unsigned long long Au = *(const unsigned long long*)&lutA[mlo][j]; \
        unsigned long long Bu = *(const unsigned long long*)&lutB[mhi][j]; \
        unsigned inc;                                                      \
        asm("{\n\t"                                                        \
            ".reg .b64 cc, ee, ff;\n\t"                                    \
            ".reg .f32 lo, hi;\n\t"                                        \
            ".reg .u32 t1, t2;\n\t"                                        \
            ".reg .pred q1, q2;\n\t"                                       \
            "add.rn.f32x2 cc, %3, %4;\n\t"                                 \
            "mov.b64 ff, {%1, %2};\n\t"                                    \
            "fma.rn.f32x2 ee, ff, %5, cc;\n\t"                             \
            "add.rn.f32x2 ff, ff, ee;\n\t"                                 \
            "mov.b64 {lo, hi}, ff;\n\t"                                    \
            "setp.ge.f32 q1, lo, 0f3F800000;\n\t"                          \
            "setp.ge.f32 q2, hi, 0f3F800000;\n\t"                          \
            "selp.f32 %1, 0f00000000, lo, q1;\n\t"                         \
            "selp.f32 %2, 0f00000000, hi, q2;\n\t"                         \
            "selp.u32 t1, %6, %7, q2;\n\t"                                 \
            "selp.u32 t2, %8, %9, q2;\n\t"                                 \
            "selp.u32 %0, t1, t2, q1;\n\t"                                 \
            "}"                                                            \
            : "=r"(inc), "+f"(vd1), "+f"(vd2)                              \
            : "l"(Au), "l"(Bu), "l"(NEG1),                                 \
              "r"(u11), "r"(u01), "r"(u10), "r"(u00));                     \
        acc += (int)inc;                                                   \
    }

    // stage A: packed PFC LIF pair + ballots straight from the predicates
    #define STAGE_A(x2v)                                                   \
    {                                                                      \
        asm volatile(                                                      \
            "{\n\t"                                                        \
            ".reg .b64 vv, dd;\n\t"                                        \
            ".reg .f32 lo, hi;\n\t"                                        \
            ".reg .pred q1, q2;\n\t"                                       \
            "mov.b64 vv, {%0, %1};\n\t"                                    \
            "fma.rn.f32x2 dd, vv, %4, %5;\n\t"                             \
            "add.rn.f32x2 vv, vv, dd;\n\t"                                 \
            "mov.b64 {lo, hi}, vv;\n\t"                                    \
            "setp.ge.f32 q1, lo, 0f3F800000;\n\t"                          \
            "setp.ge.f32 q2, hi, 0f3F800000;\n\t"                          \
            "selp.f32 %0, 0f00000000, lo, q1;\n\t"                         \
            "selp.f32 %1, 0f00000000, hi, q2;\n\t"                         \
            "vote.sync.ballot.b32 %2, q1, 0xffffffff;\n\t"                 \
            "vote.sync.ballot.b32 %3, q2, 0xffffffff;\n\t"                 \
            "}"                                                            \
            : "+f"(v0), "+f"(v1), "=r"(m_lo), "=r"(m_hi)                   \
            : "l"(NEG1), "l"(x2v));                                        \
    }

    // PFC-only halo step (packed math, no ballots, no B stage)
    #define STEP_PFC(x2v)                                                  \
    {                                                                      \
        asm("{\n\t"                                                        \
            ".reg .b64 vv, dd;\n\t"                                        \
            ".reg .f32 lo, hi;\n\t"                                        \
            ".reg .pred q1, q2;\n\t"                                       \
            "mov.b64 vv, {%0, %1};\n\t"                                    \
            "fma.rn.f32x2 dd, vv, %2, %3;\n\t"                             \
            "add.rn.f32x2 vv, vv, dd;\n\t"                                 \
            "mov.b64 {lo, hi}, vv;\n\t"                                    \
            "setp.ge.f32 q1, lo, 0f3F800000;\n\t"                          \
            "setp.ge.f32 q2, hi, 0f3F800000;\n\t"                          \
            "selp.f32 %0, 0f00000000, lo, q1;\n\t"                         \
            "selp.f32 %1, 0f00000000, hi, q2;\n\t"                         \
            "}"                                                            \
            : "+f"(v0), "+f"(v1)                                           \
            : "l"(NEG1), "l"(x2v));                                        \
    }

    // one 8-step group from packed buffer slot s, group index gi (warp-uniform)
    #define GROUP(s, gi)                                                   \
    {                                                                      \
        if ((gi) < P) {                                                    \
            _Pragma("unroll")                                              \
            for (int k = 0; k < 8; k++) STEP_PFC(x2##s[k]);                 \
        } else {                                                           \
            _Pragma("unroll")                                              \
            for (int k = 0; k < 8; k++) {                                  \
                if (k == 1 && (gi) == ZG) acc = 0;                         \
                STAGE_B();                                                 \
                STAGE_A(x2##s[k]);                                         \
            }                                                              \
        }                                                                  \
    }

    // load one group, packing (x[pos], x[pos+8]) into a 64-bit reg pair
    #define LOADG(s, ptr)                                                  \
    {                                                                      \
        _Pragma("unroll")                                                  \
        for (int k = 0; k < 8; k++) {                                      \
            float xa_ = (ptr)[k * STRIDE_T];                               \
            float xb_ = (ptr)[k * STRIDE_T + 8];                           \
            asm("mov.b64 %0, {%1, %2};"                                    \
                : "=l"(x2##s[k]) : "f"(xa_), "f"(xb_));                    \
        }                                                                  \
    }

    const float* p = pfc + (size_t)t0 * STRIDE_T + b * NS + pos;
    unsigned long long x20[8], x21[8];

    LOADG(0, p); p += 8 * STRIDE_T;   // g0
    LOADG(1, p); p += 8 * STRIDE_T;   // g1

    GROUP(0, 0);                      // g0

    #pragma unroll 1
    for (int i = 0; i < npair; i++) {
        LOADG(0, p);                  // g(2i+2), always a valid group
        p += 8 * STRIDE_T;
        GROUP(1, 2 * i + 1);          // g(2i+1)
        // final iteration's refill (past chunk/array): clamp, data unused
        const float* pb = (i < npair - 1) ? p : pfc + (b * NS + pos);
        LOADG(1, pb);
        p += 8 * STRIDE_T;
        GROUP(0, 2 * i + 2);          // g(2i+2)
    }

    STAGE_B();   // drain: count the final step

    #undef LOADG
    #undef GROUP
    #undef STEP_PFC
    #undef STAGE_A
    #undef STAGE_B

    if (pos < 4) g_part[(b * C_CHUNKS + chunk) * NA + j] = acc;

    // ---- last-block fused finalize ----
    __syncthreads();
    if (tid == 0) {
        __threadfence();
        int old = atomicAdd(&g_done, 1);
        s_last = (old == (int)gridDim.x - 1) ? 1 : 0;
    }
    __syncthreads();
    if (s_last) {
        __threadfence();   // acquire: all blocks' g_part writes visible
        for (int bb = tid; bb < BATCH; bb += 128) {
            int c0 = 0, c1 = 0, c2 = 0, c3 = 0;
            #pragma unroll
            for (int ch = 0; ch < C_CHUNKS; ch++) {
                const int4 v4 = *(const int4*)&g_part[(bb * C_CHUNKS + ch) * NA];
                c0 += v4.x; c1 += v4.y; c2 += v4.z; c3 += v4.w;
            }
            int best = 0, bv = c0;
            if (c1 > bv) { bv = c1; best = 1; }
            if (c2 > bv) { bv = c2; best = 2; }
            if (c3 > bv) { bv = c3; best = 3; }

            if (out_size == BATCH * (1 + NA)) {
                out[bb] = (float)best;
                out[BATCH + bb * NA + 0] = (float)c0;
                out[BATCH + bb * NA + 1] = (float)c1;
                out[BATCH + bb * NA + 2] = (float)c2;
                out[BATCH + bb * NA + 3] = (float)c3;
            } else if (out_size == BATCH * NA) {
                out[bb * NA + 0] = (float)c0;
                out[bb * NA + 1] = (float)c1;
                out[bb * NA + 2] = (float)c2;
                out[bb * NA + 3] = (float)c3;
            } else if (out_size == BATCH) {
                ((int*)out)[bb] = best;
            } else {
                if (bb * NA + 3 < out_size) {
                    out[bb * NA + 0] = (float)c0;
                    out[bb * NA + 1] = (float)c1;
                    out[bb * NA + 2] = (float)c2;
                    out[bb * NA + 3] = (float)c3;
                }
                if (BATCH * NA + bb < out_size) out[BATCH * NA + bb] = (float)best;
            }
        }
        if (tid == 0) g_done = 0;   // reset for next graph replay
    }
}

extern "C" void kernel_launch(void* const* d_in, const int* in_sizes, int n_in,
                              void* d_out, int out_size) {
    const float* pfc = (const float*)d_in[0];   // [2000, 1024, 16] f32
    const float* w1  = (const float*)d_in[1];   // [16, 4] f32
    const float* w2  = (const float*)d_in[2];   // [16, 4] f32

    // 256 batch-quads x 10 chunks = 2560 warps -> 640 blocks of 4 warps
    bg_kernel<<<640, 128>>>(pfc, w1, w2, (float*)d_out, out_size);
}

// round 16
// speedup vs baseline: 14.4406x; 14.4406x over previous
#include <cuda_runtime.h>
#include <stdint.h>

#define T_STEPS 2000
#define BATCH   1024
#define NS      16
#define NA      4
#define STRIDE_T (BATCH * NS)

#define C_CHUNKS 10
#define K_CHUNK  200
#define HALO     48

__device__ int g_part[BATCH * C_CHUNKS * NA];
__device__ int g_done = 0;

// ---------------------------------------------------------------------------
// Truth-table of the GPE->STN->GPI->THAL->PMC cascade for action channel j.
// These layers are exactly stateless (each sub-threshold current set has <= 1
// element, regenerated exactly; every supra-threshold current fires from any
// reachable v), so s_pmc = f(s_d1, s_d2) given by one exact LIF step per layer
// from v=0 (v' = x exactly, fire <=> x >= 1). Same fp32 op order as reference.
// Used identically on host (capture-time dispatch) and device (fallback).
// ---------------------------------------------------------------------------
__host__ __device__ inline int bg_truth_table(int j) {
    const float w1j = (j == 0) ? 0.2f : (j == 1) ? 0.12f : (j == 2) ? 0.07f : 0.03f;
    const float w2j = (j == 0) ? 0.03f : (j == 1) ? 0.07f : (j == 2) ? 0.12f : 0.2f;
    const float W_D1_GPI   = (-1.0f * w1j) * 5.0f;
    const float W_D2_GPE   = (-1.0f * w1j) * 5.0f;
    const float W_GPE_STN  = (-0.8f * w1j) * 5.0f;
    const float W_STN_GPI  = (1.2f  * w1j) * 5.0f;
    const float W_GPI_THAL = (-1.0f * w2j) * 5.0f;
    const float W_THAL_PMC = (1.0f  * w1j) * 5.0f;
    int tt = 0;
    for (int cb = 0; cb < 4; cb++) {
        float sd1 = (cb & 2) ? 1.0f : 0.0f;
        float sd2 = (cb & 1) ? 1.0f : 0.0f;
        float xg = sd2 * W_D2_GPE + 1.5f;
        float sg = (xg >= 1.0f) ? 1.0f : 0.0f;
        float xs = sg * W_GPE_STN + 1.8f;
        float ss = (xs >= 1.0f) ? 1.0f : 0.0f;
        float xi = (sd1 * W_D1_GPI + ss * W_STN_GPI) + 1.5f;
        float si = (xi >= 1.0f) ? 1.0f : 0.0f;
        float xt = si * W_GPI_THAL + 1.2f;
        float st = (xt >= 1.0f) ? 1.0f : 0.0f;
        float xp = st * W_THAL_PMC + 0.5f;
        if (xp >= 1.0f) tt |= 1 << cb;
    }
    return tt;
}

// ---------------------------------------------------------------------------
// Fast path: every tt_j is uniform (all-0 or all-15), so s_pmc(t) is constant
// per channel and pmc_totals = T_STEPS * bit, independent of all inputs.
// ---------------------------------------------------------------------------
__global__ void const_out_kernel(float* __restrict__ out, int out_size,
                                 float c0, float c1, float c2, float c3,
                                 int best)
{
    int b = blockIdx.x * blockDim.x + threadIdx.x;
    if (b >= BATCH) return;
    if (out_size == BATCH * (1 + NA)) {
        out[b] = (float)best;
        out[BATCH + b * NA + 0] = c0;
        out[BATCH + b * NA + 1] = c1;
        out[BATCH + b * NA + 2] = c2;
        out[BATCH + b * NA + 3] = c3;
    } else if (out_size == BATCH * NA) {
        out[b * NA + 0] = c0;
        out[b * NA + 1] = c1;
        out[b * NA + 2] = c2;
        out[b * NA + 3] = c3;
    } else if (out_size == BATCH) {
        ((int*)out)[b] = best;
    } else {
        if (b * NA + 3 < out_size) {
            out[b * NA + 0] = c0;
            out[b * NA + 1] = c1;
            out[b * NA + 2] = c2;
            out[b * NA + 3] = c3;
        }
        if (BATCH * NA + b < out_size) out[BATCH * NA + b] = (float)best;
    }
}

// ---------------------------------------------------------------------------
// Fallback: full renewal-chunked simulation (proven R8 kernel, 45.3us,
// rel_err 0.0). Only launched if the host-computed truth tables are ever
// non-uniform (impossible with the reference's fixed pathway constants).
// ---------------------------------------------------------------------------
__global__ __launch_bounds__(128, 5)
void bg_kernel(const float* __restrict__ pfc,
               const float* __restrict__ w_pfc_d1,
               const float* __restrict__ w_pfc_d2,
               float* __restrict__ out, int out_size)
{
    __shared__ float2 lutA[256][NA];
    __shared__ float2 lutB[256][NA];
    __shared__ int s_last;

    const int tid = threadIdx.x;
    for (int e = tid; e < 512; e += blockDim.x) {
        const int hi = e >> 8;
        const int m  = e & 255;
        const int ibase = hi ? 8 : 0;
        #pragma unroll
        for (int jj = 0; jj < NA; jj++) {
            float a1 = 0.0f, a2 = 0.0f;
            #pragma unroll
            for (int i = 0; i < 8; i++)
                if ((m >> i) & 1) {
                    a1 += w_pfc_d1[(ibase + i) * NA + jj];
                    a2 += w_pfc_d2[(ibase + i) * NA + jj];
                }
            if (hi) lutB[m][jj] = make_float2(a1, a2);
            else    lutA[m][jj] = make_float2(a1, a2);
        }
    }
    __syncthreads();

    const int lane  = tid & 31;
    const int w     = blockIdx.x * 4 + (tid >> 5);
    const int quad  = w / C_CHUNKS;
    const int chunk = w - quad * C_CHUNKS;
    const int grp   = lane >> 3;
    const int pos   = lane & 7;
    const int b     = quad * 4 + grp;
    const int j     = pos & 3;
    const unsigned full = 0xffffffffu;
    const unsigned sel = 0x4440u | (unsigned)grp;

    const int tt = bg_truth_table(j);
    const int c00 = tt & 1, c01 = (tt >> 1) & 1, c10 = (tt >> 2) & 1, c11 = (tt >> 3) & 1;

    const int t0    = chunk * K_CHUNK - (chunk ? HALO : 0);
    const int npair = chunk ? 15 : 12;
    const int P     = chunk ? 4 : 0;
    const int ZG    = chunk ? 6 : 0;

    float v0 = 0.0f, v1 = 0.0f, vd1 = 0.0f, vd2 = 0.0f;
    int acc = 0;
    unsigned m_lo = 0, m_hi = 0;

    #define STAGE_B()                                                      \
    {                                                                      \
        unsigned mlo = __byte_perm(m_lo, 0u, sel);                         \
        unsigned mhi = __byte_perm(m_hi, 0u, sel);                         \
        float2 A  = lutA[mlo][j];                                          \
        float2 Bv = lutB[mhi][j];                                          \
        float d1c = A.x + Bv.x;                                            \
        float d2c = A.y + Bv.y;                                            \
        float e1 = d1c - vd1; vd1 = vd1 + e1;                              \
        bool p1 = (vd1 >= 1.0f); vd1 = p1 ? 0.0f : vd1;                    \
        float e2 = d2c - vd2; vd2 = vd2 + e2;                              \
        bool p2 = (vd2 >= 1.0f); vd2 = p2 ? 0.0f : vd2;                    \
        acc += p1 ? (p2 ? c11 : c10) : (p2 ? c01 : c00);                   \
    }

    #define STAGE_A(xa, xb)                                                \
    {                                                                      \
        float dv0 = (xa) - v0; v0 = v0 + dv0;                              \
        bool f0 = (v0 >= 1.0f); v0 = f0 ? 0.0f : v0;                       \
        float dv1 = (xb) - v1; v1 = v1 + dv1;                              \
        bool f1 = (v1 >= 1.0f); v1 = f1 ? 0.0f : v1;                       \
        m_lo = __ballot_sync(full, f0);                                    \
        m_hi = __ballot_sync(full, f1);                                    \
    }

    #define STEP_PFC(xa, xb)                                               \
    {                                                                      \
        float dv0 = (xa) - v0; v0 = v0 + dv0;                              \
        if (v0 >= 1.0f) v0 = 0.0f;                                         \
        float dv1 = (xb) - v1; v1 = v1 + dv1;                              \
        if (v1 >= 1.0f) v1 = 0.0f;                                         \
    }

    #define GROUP(s, gi)                                                   \
    {                                                                      \
        if ((gi) < P) {                                                    \
            _Pragma("unroll")                                              \
            for (int k = 0; k < 8; k++) STEP_PFC(xa##s[k], xb##s[k]);      \
        } else {                                                           \
            _Pragma("unroll")                                              \
            for (int k = 0; k < 8; k++) {                                  \
                if (k == 1 && (gi) == ZG) acc = 0;                         \
                STAGE_B();                                                 \
                STAGE_A(xa##s[k], xb##s[k]);                               \
            }                                                              \
        }                                                                  \
    }

    #define LOADG(s, ptr)                                                  \
    {                                                                      \
        _Pragma("unroll")                                                  \
        for (int k = 0; k < 8; k++) {                                      \
            xa##s[k] = (ptr)[k * STRIDE_T];                                \
            xb##s[k] = (ptr)[k * STRIDE_T + 8];                            \
        }                                                                  \
    }

    const float* p = pfc + (size_t)t0 * STRIDE_T + b * NS + pos;
    float xa0[8], xb0[8], xa1[8], xb1[8];

    LOADG(0, p); p += 8 * STRIDE_T;
    LOADG(1, p); p += 8 * STRIDE_T;

    GROUP(0, 0);

    #pragma unroll 1
    for (int i = 0; i < npair; i++) {
        LOADG(0, p);
        p += 8 * STRIDE_T;
        GROUP(1, 2 * i + 1);
        const float* pb = (i < npair - 1) ? p : pfc + (b * NS + pos);
        LOADG(1, pb);
        p += 8 * STRIDE_T;
        GROUP(0, 2 * i + 2);
    }

    STAGE_B();

    #undef LOADG
    #undef GROUP
    #undef STEP_PFC
    #undef STAGE_A
    #undef STAGE_B

    if (pos < 4) g_part[(b * C_CHUNKS + chunk) * NA + j] = acc;

    __syncthreads();
    if (tid == 0) {
        __threadfence();
        int old = atomicAdd(&g_done, 1);
        s_last = (old == (int)gridDim.x - 1) ? 1 : 0;
    }
    __syncthreads();
    if (s_last) {
        __threadfence();
        for (int bb = tid; bb < BATCH; bb += 128) {
            int c0 = 0, c1 = 0, c2 = 0, c3 = 0;
            #pragma unroll
            for (int ch = 0; ch < C_CHUNKS; ch++) {
                const int4 v4 = *(const int4*)&g_part[(bb * C_CHUNKS + ch) * NA];
                c0 += v4.x; c1 += v4.y; c2 += v4.z; c3 += v4.w;
            }
            int best = 0, bv = c0;
            if (c1 > bv) { bv = c1; best = 1; }
            if (c2 > bv) { bv = c2; best = 2; }
            if (c3 > bv) { bv = c3; best = 3; }

            if (out_size == BATCH * (1 + NA)) {
                out[bb] = (float)best;
                out[BATCH + bb * NA + 0] = (float)c0;
                out[BATCH + bb * NA + 1] = (float)c1;
                out[BATCH + bb * NA + 2] = (float)c2;
                out[BATCH + bb * NA + 3] = (float)c3;
            } else if (out_size == BATCH * NA) {
                out[bb * NA + 0] = (float)c0;
                out[bb * NA + 1] = (float)c1;
                out[bb * NA + 2] = (float)c2;
                out[bb * NA + 3] = (float)c3;
            } else if (out_size == BATCH) {
                ((int*)out)[bb] = best;
            } else {
                if (bb * NA + 3 < out_size) {
                    out[bb * NA + 0] = (float)c0;
                    out[bb * NA + 1] = (float)c1;
                    out[bb * NA + 2] = (float)c2;
                    out[bb * NA + 3] = (float)c3;
                }
                if (BATCH * NA + bb < out_size) out[BATCH * NA + bb] = (float)best;
            }
        }
        if (tid == 0) g_done = 0;
    }
}

extern "C" void kernel_launch(void* const* d_in, const int* in_sizes, int n_in,
                              void* d_out, int out_size) {
    const float* pfc = (const float*)d_in[0];   // [2000, 1024, 16] f32
    const float* w1  = (const float*)d_in[1];   // [16, 4] f32
    const float* w2  = (const float*)d_in[2];   // [16, 4] f32

    // Capture-time dispatch on compile-time constants only (deterministic,
    // no device reads): if every channel's cascade truth table is uniform,
    // s_pmc(t) is input-independent and the totals are T_STEPS * bit.
    int tt0 = bg_truth_table(0);
    int tt1 = bg_truth_table(1);
    int tt2 = bg_truth_table(2);
    int tt3 = bg_truth_table(3);
    bool uni = (tt0 == 0 || tt0 == 15) && (tt1 == 0 || tt1 == 15) &&
               (tt2 == 0 || tt2 == 15) && (tt3 == 0 || tt3 == 15);

    if (uni) {
        float c0 = (tt0 & 1) ? (float)T_STEPS : 0.0f;
        float c1 = (tt1 & 1) ? (float)T_STEPS : 0.0f;
        float c2 = (tt2 & 1) ? (float)T_STEPS : 0.0f;
        float c3 = (tt3 & 1) ? (float)T_STEPS : 0.0f;
        int best = 0; float bv = c0;
        if (c1 > bv) { bv = c1; best = 1; }
        if (c2 > bv) { bv = c2; best = 2; }
        if (c3 > bv) { bv = c3; best = 3; }
        const_out_kernel<<<(BATCH + 127) / 128, 128>>>((float*)d_out, out_size,
                                                       c0, c1, c2, c3, best);
    } else {
        bg_kernel<<<640, 128>>>(pfc, w1, w2, (float*)d_out, out_size);
    }
}